// round 1
// baseline (speedup 1.0000x reference)
#include <cuda_runtime.h>
#include <math.h>

#define SQ   2048   // sequence length (tokens, B=1)
#define HID  1024   // hidden
#define NH   16     // heads
#define HD   64     // head dim
#define H3   3072   // 3*HID
#define NE   8      // experts
#define TK   2      // top-k
#define FF   2048   // ffn hidden

// ---------------- scratch (device globals; allocation-free) ----------------
__device__ float g_hn   [SQ*HID];
__device__ float g_qkv  [SQ*H3];
__device__ float g_scores[(size_t)NH*SQ*SQ];   // 256 MB
__device__ float g_attn [SQ*HID];
__device__ float g_x1   [SQ*HID];
__device__ float g_hn2  [SQ*HID];
__device__ int   g_topi [SQ*TK];
__device__ float g_topw [SQ*TK];
__device__ int   g_tok  [NE*SQ];
__device__ float g_gate [NE*SQ];
__device__ int   g_slot [NE*SQ];
__device__ int   g_cnt  [NE];
__device__ float g_h1   [(size_t)NE*SQ*FF];    // 128 MB
__device__ float g_y2   [SQ*TK*HID];

// ---------------- shared micro-kernel: 64x64 tile, 4x4 per thread ----------
__device__ __forceinline__ void mm16(const float (*As)[64], const float (*Bs)[64],
                                     float acc[4][4], int tx, int ty) {
#pragma unroll
    for (int kk = 0; kk < 16; kk++) {
        float4 a = *(const float4*)(&As[kk][ty*4]);
        float4 b = *(const float4*)(&Bs[kk][tx*4]);
        acc[0][0]+=a.x*b.x; acc[0][1]+=a.x*b.y; acc[0][2]+=a.x*b.z; acc[0][3]+=a.x*b.w;
        acc[1][0]+=a.y*b.x; acc[1][1]+=a.y*b.y; acc[1][2]+=a.y*b.z; acc[1][3]+=a.y*b.w;
        acc[2][0]+=a.z*b.x; acc[2][1]+=a.z*b.y; acc[2][2]+=a.z*b.z; acc[2][3]+=a.z*b.w;
        acc[3][0]+=a.w*b.x; acc[3][1]+=a.w*b.y; acc[3][2]+=a.w*b.z; acc[3][3]+=a.w*b.w;
    }
}

// ---------------- layernorm: one block per token ----------------
__global__ void ln_kernel(const float* __restrict__ x, const float* __restrict__ w,
                          const float* __restrict__ b, float* __restrict__ out) {
    int t = blockIdx.x, tid = threadIdx.x;
    float4 v = ((const float4*)(x + (size_t)t*HID))[tid];
    __shared__ float red[256];
    red[tid] = v.x+v.y+v.z+v.w; __syncthreads();
    for (int o = 128; o > 0; o >>= 1) { if (tid < o) red[tid] += red[tid+o]; __syncthreads(); }
    float mu = red[0] * (1.0f/HID); __syncthreads();
    float dx=v.x-mu, dy=v.y-mu, dz=v.z-mu, dw=v.w-mu;
    red[tid] = dx*dx+dy*dy+dz*dz+dw*dw; __syncthreads();
    for (int o = 128; o > 0; o >>= 1) { if (tid < o) red[tid] += red[tid+o]; __syncthreads(); }
    float rstd = rsqrtf(red[0] * (1.0f/HID) + 1e-5f);
    float4 wv = ((const float4*)w)[tid];
    float4 bv = ((const float4*)b)[tid];
    float4 o4;
    o4.x = dx*rstd*wv.x + bv.x; o4.y = dy*rstd*wv.y + bv.y;
    o4.z = dz*rstd*wv.z + bv.z; o4.w = dw*rstd*wv.w + bv.w;
    ((float4*)(out + (size_t)t*HID))[tid] = o4;
}

// ---------------- C[M,N] = A[M,K] * B[N,K]^T + bias (+res) ----------------
template<bool ADD_RES>
__global__ void gemm_nt(const float* __restrict__ A, const float* __restrict__ B,
                        const float* __restrict__ bias, const float* __restrict__ res,
                        float* __restrict__ C, int M, int N, int Kd) {
    __shared__ float As[16][64], Bs[16][64];
    int tid = threadIdx.x, tx = tid & 15, ty = tid >> 4;
    int m0 = blockIdx.y * 64, n0 = blockIdx.x * 64;
    int lr = tid >> 2, lk = (tid & 3) * 4;
    float acc[4][4] = {};
    for (int k0 = 0; k0 < Kd; k0 += 16) {
        float4 av = *(const float4*)(A + (size_t)(m0+lr)*Kd + k0 + lk);
        float4 bv = *(const float4*)(B + (size_t)(n0+lr)*Kd + k0 + lk);
        As[lk+0][lr]=av.x; As[lk+1][lr]=av.y; As[lk+2][lr]=av.z; As[lk+3][lr]=av.w;
        Bs[lk+0][lr]=bv.x; Bs[lk+1][lr]=bv.y; Bs[lk+2][lr]=bv.z; Bs[lk+3][lr]=bv.w;
        __syncthreads();
        mm16(As, Bs, acc, tx, ty);
        __syncthreads();
    }
#pragma unroll
    for (int i = 0; i < 4; i++)
#pragma unroll
        for (int j = 0; j < 4; j++) {
            int m = m0 + ty*4 + i, n = n0 + tx*4 + j;
            float v = acc[i][j] + bias[n];
            if (ADD_RES) v += res[(size_t)m*N + n];
            C[(size_t)m*N + n] = v;
        }
}

// ---------------- scores[h] = Q_h K_h^T * 1/8 (skip fully-masked tiles) ----
__global__ void scores_kernel(const float* __restrict__ qkv, float* __restrict__ scores) {
    int h = blockIdx.z;
    int m0 = blockIdx.y * 64, n0 = blockIdx.x * 64;
    if (m0 + 63 < n0) return;   // entire tile above diagonal
    __shared__ float As[16][64], Bs[16][64];
    int tid = threadIdx.x, tx = tid & 15, ty = tid >> 4;
    int lr = tid >> 2, lk = (tid & 3) * 4;
    const float* Q = qkv + h*HD;
    const float* K = qkv + HID + h*HD;
    float acc[4][4] = {};
    for (int k0 = 0; k0 < HD; k0 += 16) {
        float4 av = *(const float4*)(Q + (size_t)(m0+lr)*H3 + k0 + lk);
        float4 bv = *(const float4*)(K + (size_t)(n0+lr)*H3 + k0 + lk);
        As[lk+0][lr]=av.x; As[lk+1][lr]=av.y; As[lk+2][lr]=av.z; As[lk+3][lr]=av.w;
        Bs[lk+0][lr]=bv.x; Bs[lk+1][lr]=bv.y; Bs[lk+2][lr]=bv.z; Bs[lk+3][lr]=bv.w;
        __syncthreads();
        mm16(As, Bs, acc, tx, ty);
        __syncthreads();
    }
    float* out = scores + (size_t)h*SQ*SQ;
#pragma unroll
    for (int i = 0; i < 4; i++)
#pragma unroll
        for (int j = 0; j < 4; j++) {
            int m = m0 + ty*4 + i, n = n0 + tx*4 + j;
            out[(size_t)m*SQ + n] = acc[i][j] * 0.125f;
        }
}

// ---------------- row softmax with causal mask (writes zeros above diag) ---
__global__ void softmax_kernel(float* __restrict__ scores) {
    int i = blockIdx.x, h = blockIdx.y, tid = threadIdx.x;
    float* row = scores + ((size_t)h*SQ + i)*SQ;
    int n = i + 1;
    __shared__ float red[256];
    float m = -1e30f;
    for (int j = tid; j < n; j += 256) m = fmaxf(m, row[j]);
    red[tid] = m; __syncthreads();
    for (int o = 128; o > 0; o >>= 1) { if (tid < o) red[tid] = fmaxf(red[tid], red[tid+o]); __syncthreads(); }
    m = red[0]; __syncthreads();
    float s = 0.f;
    for (int j = tid; j < n; j += 256) { float e = __expf(row[j] - m); row[j] = e; s += e; }
    red[tid] = s; __syncthreads();
    for (int o = 128; o > 0; o >>= 1) { if (tid < o) red[tid] += red[tid+o]; __syncthreads(); }
    float inv = 1.0f / red[0];
    for (int j = tid; j < n; j += 256) row[j] *= inv;
    for (int j = n + tid; j < SQ; j += 256) row[j] = 0.f;
}

// ---------------- attn[:, h] = P_h V_h (k-tiles truncated at diagonal) -----
__global__ void pv_kernel(const float* __restrict__ scores, const float* __restrict__ qkv,
                          float* __restrict__ attn) {
    int h = blockIdx.z, m0 = blockIdx.y * 64;
    __shared__ float As[16][64], Bs[16][64];
    int tid = threadIdx.x, tx = tid & 15, ty = tid >> 4;
    int lr = tid >> 2, lk = (tid & 3) * 4;
    int bk = tid >> 4, bn = (tid & 15) * 4;
    const float* P = scores + (size_t)h*SQ*SQ;
    const float* V = qkv + 2*HID + h*HD;
    int ktiles = (m0 + 64) / 16;          // keys beyond diagonal have P==0
    float acc[4][4] = {};
    for (int kt = 0; kt < ktiles; kt++) {
        int k0 = kt * 16;
        float4 av = *(const float4*)(P + (size_t)(m0+lr)*SQ + k0 + lk);
        As[lk+0][lr]=av.x; As[lk+1][lr]=av.y; As[lk+2][lr]=av.z; As[lk+3][lr]=av.w;
        float4 bv = *(const float4*)(V + (size_t)(k0+bk)*H3 + bn);
        Bs[bk][bn+0]=bv.x; Bs[bk][bn+1]=bv.y; Bs[bk][bn+2]=bv.z; Bs[bk][bn+3]=bv.w;
        __syncthreads();
        mm16(As, Bs, acc, tx, ty);
        __syncthreads();
    }
#pragma unroll
    for (int i = 0; i < 4; i++)
#pragma unroll
        for (int j = 0; j < 4; j++) {
            int m = m0 + ty*4 + i, n = tx*4 + j;
            attn[(size_t)m*HID + h*HD + n] = acc[i][j];
        }
}

// ---------------- router: logits, softmax(8), top-2 ----------------
__global__ void router_kernel(const float* __restrict__ hn2, const float* __restrict__ rw) {
    int t = blockIdx.x, tid = threadIdx.x;
    __shared__ float part[NE][256];
    float loc[NE] = {};
    for (int hh = tid; hh < HID; hh += 256) {
        float xv = hn2[(size_t)t*HID + hh];
#pragma unroll
        for (int e = 0; e < NE; e++) loc[e] += xv * rw[e*HID + hh];
    }
#pragma unroll
    for (int e = 0; e < NE; e++) part[e][tid] = loc[e];
    __syncthreads();
    for (int o = 128; o > 0; o >>= 1) {
        if (tid < o)
#pragma unroll
            for (int e = 0; e < NE; e++) part[e][tid] += part[e][tid+o];
        __syncthreads();
    }
    if (tid == 0) {
        float lg[NE], mx = -1e30f;
#pragma unroll
        for (int e = 0; e < NE; e++) { lg[e] = part[e][0]; mx = fmaxf(mx, lg[e]); }
        float s = 0.f;
#pragma unroll
        for (int e = 0; e < NE; e++) { lg[e] = expf(lg[e]-mx); s += lg[e]; }
        float inv = 1.0f/s;
#pragma unroll
        for (int e = 0; e < NE; e++) lg[e] *= inv;
        int i0 = 0; float v0 = lg[0];
#pragma unroll
        for (int e = 1; e < NE; e++) if (lg[e] > v0) { v0 = lg[e]; i0 = e; }
        int i1 = -1; float v1 = -1e30f;
#pragma unroll
        for (int e = 0; e < NE; e++) if (e != i0 && lg[e] > v1) { v1 = lg[e]; i1 = e; }
        g_topi[t*TK+0] = i0; g_topw[t*TK+0] = v0;
        g_topi[t*TK+1] = i1; g_topw[t*TK+1] = v1;
    }
}

// ---------------- deterministic per-expert token lists (no atomics) --------
__global__ void build_lists_kernel() {
    int e = blockIdx.x, tid = threadIdx.x;
    const int CH = SQ / 256;  // 8 tokens per thread
    int ids[CH], slots[CH]; float gs[CH];
    int loc = 0;
    for (int c = 0; c < CH; c++) {
        int t = tid*CH + c;
        if (g_topi[t*TK+0] == e)      { ids[loc]=t; slots[loc]=0; gs[loc]=g_topw[t*TK+0]; loc++; }
        else if (g_topi[t*TK+1] == e) { ids[loc]=t; slots[loc]=1; gs[loc]=g_topw[t*TK+1]; loc++; }
    }
    __shared__ int sc[256];
    sc[tid] = loc; __syncthreads();
    for (int o = 1; o < 256; o <<= 1) {
        int v = (tid >= o) ? sc[tid-o] : 0;
        __syncthreads();
        sc[tid] += v;
        __syncthreads();
    }
    int off = sc[tid] - loc;
    for (int c = 0; c < loc; c++) {
        g_tok [e*SQ + off + c] = ids[c];
        g_slot[e*SQ + off + c] = slots[c];
        g_gate[e*SQ + off + c] = gs[c];
    }
    if (tid == 255) g_cnt[e] = sc[255];
}

__device__ __forceinline__ float gelu_exact(float x) {
    return 0.5f * x * (1.0f + erff(x * 0.70710678118654752f));
}

// ---------------- expert GEMM1: h1 = gelu(gather(hn2) @ w1[e]) -------------
__global__ void moe1_kernel(const float* __restrict__ hn2, const float* __restrict__ w1) {
    int e = blockIdx.z;
    int cnt = g_cnt[e];
    int m0 = blockIdx.y * 64;
    if (m0 >= cnt) return;
    int n0 = blockIdx.x * 64;
    __shared__ float As[16][64], Bs[16][64];
    int tid = threadIdx.x, tx = tid & 15, ty = tid >> 4;
    int lr = tid >> 2, lk = (tid & 3) * 4;
    int bk = tid >> 4, bn = (tid & 15) * 4;
    const float* W = w1 + (size_t)e*HID*FF;
    int r = m0 + lr;
    int tok = (r < cnt) ? g_tok[e*SQ + r] : -1;
    float acc[4][4] = {};
    for (int k0 = 0; k0 < HID; k0 += 16) {
        float4 av = make_float4(0,0,0,0);
        if (tok >= 0) av = *(const float4*)(hn2 + (size_t)tok*HID + k0 + lk);
        As[lk+0][lr]=av.x; As[lk+1][lr]=av.y; As[lk+2][lr]=av.z; As[lk+3][lr]=av.w;
        float4 bv = *(const float4*)(W + (size_t)(k0+bk)*FF + n0 + bn);
        Bs[bk][bn+0]=bv.x; Bs[bk][bn+1]=bv.y; Bs[bk][bn+2]=bv.z; Bs[bk][bn+3]=bv.w;
        __syncthreads();
        mm16(As, Bs, acc, tx, ty);
        __syncthreads();
    }
    float* H1 = g_h1 + (size_t)e*SQ*FF;
#pragma unroll
    for (int i = 0; i < 4; i++) {
        int rr = m0 + ty*4 + i;
        if (rr < cnt)
#pragma unroll
            for (int j = 0; j < 4; j++)
                H1[(size_t)rr*FF + n0 + tx*4 + j] = gelu_exact(acc[i][j]);
    }
}

// ---------------- expert GEMM2: y2[tok,slot] = gate * (h1 @ w2[e]) ---------
__global__ void moe2_kernel(const float* __restrict__ w2) {
    int e = blockIdx.z;
    int cnt = g_cnt[e];
    int m0 = blockIdx.y * 64;
    if (m0 >= cnt) return;
    int n0 = blockIdx.x * 64;
    __shared__ float As[16][64], Bs[16][64];
    int tid = threadIdx.x, tx = tid & 15, ty = tid >> 4;
    int lr = tid >> 2, lk = (tid & 3) * 4;
    int bk = tid >> 4, bn = (tid & 15) * 4;
    const float* A = g_h1 + (size_t)e*SQ*FF;
    const float* W = w2 + (size_t)e*FF*HID;
    int r = m0 + lr;
    bool rv = (r < cnt);
    float acc[4][4] = {};
    for (int k0 = 0; k0 < FF; k0 += 16) {
        float4 av = make_float4(0,0,0,0);
        if (rv) av = *(const float4*)(A + (size_t)r*FF + k0 + lk);
        As[lk+0][lr]=av.x; As[lk+1][lr]=av.y; As[lk+2][lr]=av.z; As[lk+3][lr]=av.w;
        float4 bv = *(const float4*)(W + (size_t)(k0+bk)*HID + n0 + bn);
        Bs[bk][bn+0]=bv.x; Bs[bk][bn+1]=bv.y; Bs[bk][bn+2]=bv.z; Bs[bk][bn+3]=bv.w;
        __syncthreads();
        mm16(As, Bs, acc, tx, ty);
        __syncthreads();
    }
#pragma unroll
    for (int i = 0; i < 4; i++) {
        int rr = m0 + ty*4 + i;
        if (rr < cnt) {
            int t = g_tok[e*SQ + rr];
            int sl = g_slot[e*SQ + rr];
            float g = g_gate[e*SQ + rr];
#pragma unroll
            for (int j = 0; j < 4; j++)
                g_y2[((size_t)t*TK + sl)*HID + n0 + tx*4 + j] = g * acc[i][j];
        }
    }
}

// ---------------- out = x1 + y2[:,0] + y2[:,1] ----------------
__global__ void final_kernel(float* __restrict__ out) {
    int idx = blockIdx.x * 256 + threadIdx.x;   // SQ*HID total
    int t = idx / HID, hh = idx % HID;
    out[idx] = g_x1[idx] + g_y2[((size_t)t*TK)*HID + hh] + g_y2[((size_t)t*TK + 1)*HID + hh];
}

// ---------------- launch ----------------
extern "C" void kernel_launch(void* const* d_in, const int* in_sizes, int n_in,
                              void* d_out, int out_size) {
    (void)in_sizes; (void)n_in; (void)out_size;
    const float* x          = (const float*)d_in[0];
    const float* ln1_w      = (const float*)d_in[1];
    const float* ln1_b      = (const float*)d_in[2];
    const float* in_proj_w  = (const float*)d_in[3];
    const float* in_proj_b  = (const float*)d_in[4];
    const float* out_proj_w = (const float*)d_in[5];
    const float* out_proj_b = (const float*)d_in[6];
    const float* ln2_w      = (const float*)d_in[7];
    const float* ln2_b      = (const float*)d_in[8];
    const float* router_w   = (const float*)d_in[9];
    const float* w1         = (const float*)d_in[10];
    const float* w2         = (const float*)d_in[11];
    float* out = (float*)d_out;

    float *hn, *qkv, *scores, *attn, *x1, *hn2;
    cudaGetSymbolAddress((void**)&hn,     g_hn);
    cudaGetSymbolAddress((void**)&qkv,    g_qkv);
    cudaGetSymbolAddress((void**)&scores, g_scores);
    cudaGetSymbolAddress((void**)&attn,   g_attn);
    cudaGetSymbolAddress((void**)&x1,     g_x1);
    cudaGetSymbolAddress((void**)&hn2,    g_hn2);

    // 1. LN1
    ln_kernel<<<SQ, 256>>>(x, ln1_w, ln1_b, hn);
    // 2. QKV = hn @ in_proj_w^T + b      [2048 x 3072 x 1024]
    gemm_nt<false><<<dim3(H3/64, SQ/64), 256>>>(hn, in_proj_w, in_proj_b, nullptr, qkv, SQ, H3, HID);
    // 3. scores = Q K^T / 8 per head
    scores_kernel<<<dim3(SQ/64, SQ/64, NH), 256>>>(qkv, scores);
    // 4. causal softmax
    softmax_kernel<<<dim3(SQ, NH), 256>>>(scores);
    // 5. attn = P V per head
    pv_kernel<<<dim3(1, SQ/64, NH), 256>>>(scores, qkv, attn);
    // 6. x1 = x + attn @ out_proj_w^T + b
    gemm_nt<true><<<dim3(HID/64, SQ/64), 256>>>(attn, out_proj_w, out_proj_b, x, x1, SQ, HID, HID);
    // 7. LN2
    ln_kernel<<<SQ, 256>>>(x1, ln2_w, ln2_b, hn2);
    // 8. router top-2
    router_kernel<<<SQ, 256>>>(hn2, router_w);
    // 9. deterministic expert lists
    build_lists_kernel<<<NE, 256>>>();
    // 10. expert GEMM1 + GELU
    moe1_kernel<<<dim3(FF/64, SQ/64, NE), 256>>>(hn2, w1);
    // 11. expert GEMM2 + gate + scatter
    moe2_kernel<<<dim3(HID/64, SQ/64, NE), 256>>>(w2);
    // 12. out = x1 + y
    final_kernel<<<(SQ*HID)/256, 256>>>(out);
}

// round 2
// speedup vs baseline: 2.6736x; 2.6736x over previous
#include <cuda_runtime.h>
#include <math.h>
#include <stdint.h>

#define SQ   2048
#define HID  1024
#define NH   16
#define HD   64
#define H3   3072
#define NE   8
#define TK   2
#define FF   2048

// ---------------- scratch ----------------
__device__ float g_hn   [SQ*HID];
__device__ float g_qkv  [SQ*H3];
__device__ float g_attn [SQ*HID];
__device__ float g_x1   [SQ*HID];
__device__ float g_hn2  [SQ*HID];
__device__ int   g_topi [SQ*TK];
__device__ float g_topw [SQ*TK];
__device__ int   g_tok  [NE*SQ];
__device__ float g_gate [NE*SQ];
__device__ int   g_slot [NE*SQ];
__device__ int   g_cnt  [NE];
__device__ float g_h1   [(size_t)NE*SQ*FF];
__device__ float g_y2   [SQ*TK*HID];

// ---------------- tf32 helpers ----------------
__device__ __forceinline__ float tf32r(float x) {
    uint32_t u; asm("cvt.rna.tf32.f32 %0, %1;" : "=r"(u) : "f"(x));
    return __uint_as_float(u);
}
__device__ __forceinline__ void mma8(float* c, float a0, float a1, float a2, float a3,
                                     float b0, float b1) {
    uint32_t A0=__float_as_uint(a0), A1=__float_as_uint(a1),
             A2=__float_as_uint(a2), A3=__float_as_uint(a3),
             B0=__float_as_uint(b0), B1=__float_as_uint(b1);
    asm volatile("mma.sync.aligned.m16n8k8.row.col.f32.tf32.tf32.f32 "
        "{%0,%1,%2,%3},{%4,%5,%6,%7},{%8,%9},{%0,%1,%2,%3};\n"
        : "+f"(c[0]), "+f"(c[1]), "+f"(c[2]), "+f"(c[3])
        : "r"(A0), "r"(A1), "r"(A2), "r"(A3), "r"(B0), "r"(B1));
}
__device__ __forceinline__ float gelu_exact(float x) {
    return 0.5f * x * (1.0f + erff(x * 0.70710678118654752f));
}

// ---------------- layernorm ----------------
__global__ void ln_kernel(const float* __restrict__ x, const float* __restrict__ w,
                          const float* __restrict__ b, float* __restrict__ out) {
    int t = blockIdx.x, tid = threadIdx.x;
    float4 v = ((const float4*)(x + (size_t)t*HID))[tid];
    __shared__ float red[256];
    red[tid] = v.x+v.y+v.z+v.w; __syncthreads();
    for (int o = 128; o > 0; o >>= 1) { if (tid < o) red[tid] += red[tid+o]; __syncthreads(); }
    float mu = red[0] * (1.0f/HID); __syncthreads();
    float dx=v.x-mu, dy=v.y-mu, dz=v.z-mu, dw=v.w-mu;
    red[tid] = dx*dx+dy*dy+dz*dz+dw*dw; __syncthreads();
    for (int o = 128; o > 0; o >>= 1) { if (tid < o) red[tid] += red[tid+o]; __syncthreads(); }
    float rstd = rsqrtf(red[0] * (1.0f/HID) + 1e-5f);
    float4 wv = ((const float4*)w)[tid];
    float4 bv = ((const float4*)b)[tid];
    float4 o4;
    o4.x = dx*rstd*wv.x + bv.x; o4.y = dy*rstd*wv.y + bv.y;
    o4.z = dz*rstd*wv.z + bv.z; o4.w = dw*rstd*wv.w + bv.w;
    ((float4*)(out + (size_t)t*HID))[tid] = o4;
}

// ================= tf32 mma GEMM =================
// MODE 0: QKV  (NT, +bias)               C = A[M,K] * B[N,K]^T + bias
// MODE 1: OUT  (NT, +bias +res)
// MODE 2: MOE1 (NN, gather A, gelu -> g_h1)
// MODE 3: MOE3 (NN, A=g_h1, gate*scatter -> g_y2)
#define BM 128
#define BN 128
#define BKg 16

template<int MODE>
__global__ void __launch_bounds__(256) mma_gemm(
        const float* __restrict__ A, const float* __restrict__ Bm,
        const float* __restrict__ bias, const float* __restrict__ res,
        float* __restrict__ C, int M, int N, int Kd) {
    __shared__ float As[BKg][BM+8];
    __shared__ float Bs[BKg][BN+8];
    int tid = threadIdx.x, wid = tid>>5, lid = tid&31;
    int g = lid>>2, tg = lid&3;
    int wm = (wid>>2)*64, wn = (wid&3)*32;
    int n0 = blockIdx.x*BN, m0 = blockIdx.y*BM;

    int e = 0, cnt = M;
    if (MODE >= 2) { e = blockIdx.z; cnt = g_cnt[e]; if (m0 >= cnt) return; }

    int arow = tid>>1;
    const float* Aptr = nullptr;
    if (MODE <= 1) {
        Aptr = A + (size_t)(m0+arow)*Kd;
    } else if (MODE == 2) {
        int t = (m0+arow < cnt) ? g_tok[e*SQ + m0 + arow] : -1;
        if (t >= 0) Aptr = A + (size_t)t*Kd;
    } else {
        int rr = m0 + arow; if (rr > SQ-1) rr = SQ-1;
        Aptr = g_h1 + (size_t)(e*SQ + rr)*Kd;
    }
    const float* Bbase = Bm;
    if (MODE >= 2) Bbase += (size_t)e * Kd * N;

    float4 aR[2], bR[2];

    auto loadA = [&](int k0) {
#pragma unroll
        for (int i = 0; i < 2; i++) {
            if (Aptr) aR[i] = *(const float4*)(Aptr + k0 + ((tid&1) + i*2)*4);
            else      aR[i] = make_float4(0,0,0,0);
        }
    };
    auto storeA = [&]() {
#pragma unroll
        for (int i = 0; i < 2; i++) {
            int kb = ((tid&1) + i*2)*4;
            As[kb+0][arow] = tf32r(aR[i].x);
            As[kb+1][arow] = tf32r(aR[i].y);
            As[kb+2][arow] = tf32r(aR[i].z);
            As[kb+3][arow] = tf32r(aR[i].w);
        }
    };
    auto loadB = [&](int k0) {
        if (MODE <= 1) {
            int nrow = tid>>1;
#pragma unroll
            for (int i = 0; i < 2; i++)
                bR[i] = *(const float4*)(Bbase + (size_t)(n0+nrow)*Kd + k0 + ((tid&1)+i*2)*4);
        } else {
            int kk = tid>>4;
#pragma unroll
            for (int i = 0; i < 2; i++)
                bR[i] = *(const float4*)(Bbase + (size_t)(k0+kk)*N + n0 + ((tid&15) + i*16)*4);
        }
    };
    auto storeB = [&]() {
        if (MODE <= 1) {
            int nrow = tid>>1;
#pragma unroll
            for (int i = 0; i < 2; i++) {
                int kb = ((tid&1) + i*2)*4;
                Bs[kb+0][nrow] = tf32r(bR[i].x);
                Bs[kb+1][nrow] = tf32r(bR[i].y);
                Bs[kb+2][nrow] = tf32r(bR[i].z);
                Bs[kb+3][nrow] = tf32r(bR[i].w);
            }
        } else {
            int kk = tid>>4;
#pragma unroll
            for (int i = 0; i < 2; i++) {
                int nn = ((tid&15) + i*16)*4;
                Bs[kk][nn+0] = tf32r(bR[i].x);
                Bs[kk][nn+1] = tf32r(bR[i].y);
                Bs[kk][nn+2] = tf32r(bR[i].z);
                Bs[kk][nn+3] = tf32r(bR[i].w);
            }
        }
    };

    float acc[4][4][4] = {};
    int KT = Kd / BKg;
    loadA(0); loadB(0); storeA(); storeB();
    for (int kt = 0; kt < KT; kt++) {
        __syncthreads();
        if (kt+1 < KT) { loadA((kt+1)*BKg); loadB((kt+1)*BKg); }
#pragma unroll
        for (int ks = 0; ks < 2; ks++) {
            float af[4][4], bf[4][2];
#pragma unroll
            for (int mi = 0; mi < 4; mi++) {
                int rb = wm + mi*16;
                af[mi][0] = As[ks*8+tg  ][rb+g];
                af[mi][1] = As[ks*8+tg  ][rb+g+8];
                af[mi][2] = As[ks*8+tg+4][rb+g];
                af[mi][3] = As[ks*8+tg+4][rb+g+8];
            }
#pragma unroll
            for (int ni = 0; ni < 4; ni++) {
                bf[ni][0] = Bs[ks*8+tg  ][wn+ni*8+g];
                bf[ni][1] = Bs[ks*8+tg+4][wn+ni*8+g];
            }
#pragma unroll
            for (int mi = 0; mi < 4; mi++)
#pragma unroll
                for (int ni = 0; ni < 4; ni++)
                    mma8(acc[mi][ni], af[mi][0], af[mi][1], af[mi][2], af[mi][3],
                         bf[ni][0], bf[ni][1]);
        }
        __syncthreads();
        if (kt+1 < KT) { storeA(); storeB(); }
    }

    // epilogue
#pragma unroll
    for (int mi = 0; mi < 4; mi++) {
        int r1 = m0 + wm + mi*16 + g;
        int r2 = r1 + 8;
#pragma unroll
        for (int ni = 0; ni < 4; ni++) {
            int cc = n0 + wn + ni*8 + 2*tg;
            float* a = acc[mi][ni];
            if (MODE == 0 || MODE == 1) {
                float b0 = bias[cc], b1 = bias[cc+1];
                float v00 = a[0]+b0, v01 = a[1]+b1, v10 = a[2]+b0, v11 = a[3]+b1;
                if (MODE == 1) {
                    v00 += res[(size_t)r1*N + cc];   v01 += res[(size_t)r1*N + cc+1];
                    v10 += res[(size_t)r2*N + cc];   v11 += res[(size_t)r2*N + cc+1];
                }
                *(float2*)(C + (size_t)r1*N + cc) = make_float2(v00, v01);
                *(float2*)(C + (size_t)r2*N + cc) = make_float2(v10, v11);
            } else if (MODE == 2) {
                if (r1 < cnt)
                    *(float2*)(&g_h1[(size_t)(e*SQ + r1)*FF + cc]) =
                        make_float2(gelu_exact(a[0]), gelu_exact(a[1]));
                if (r2 < cnt)
                    *(float2*)(&g_h1[(size_t)(e*SQ + r2)*FF + cc]) =
                        make_float2(gelu_exact(a[2]), gelu_exact(a[3]));
            } else {
                if (r1 < cnt) {
                    int t = g_tok[e*SQ+r1], sl = g_slot[e*SQ+r1];
                    float gt = g_gate[e*SQ+r1];
                    *(float2*)(&g_y2[((size_t)t*TK+sl)*HID + cc]) =
                        make_float2(gt*a[0], gt*a[1]);
                }
                if (r2 < cnt) {
                    int t = g_tok[e*SQ+r2], sl = g_slot[e*SQ+r2];
                    float gt = g_gate[e*SQ+r2];
                    *(float2*)(&g_y2[((size_t)t*TK+sl)*HID + cc]) =
                        make_float2(gt*a[2], gt*a[3]);
                }
            }
        }
    }
}

// ================= flash attention (tf32 mma, online softmax) =================
#define FBM 128
__global__ void __launch_bounds__(256) flash_kernel(const float* __restrict__ qkv,
                                                    float* __restrict__ attn) {
    int h = blockIdx.y;
    int q0 = blockIdx.x * FBM;
    int tid = threadIdx.x, wid = tid>>5, lid = tid&31;
    int wm = wid*16;
    int g = lid>>2, tg = lid&3;
    __shared__ float Ks[64][72];   // [d][kv]
    __shared__ float Vs[64][72];   // [kv][d]

    // Q fragments (16 rows per warp x 64 d), pre-scaled by 1/8, tf32
    float qf[8][4];
    {
        const float* Q = qkv + (size_t)(q0+wm)*H3 + h*HD;
#pragma unroll
        for (int kc = 0; kc < 8; kc++) {
            int c = kc*8 + tg;
            qf[kc][0] = tf32r(Q[(size_t)g*H3     + c    ] * 0.125f);
            qf[kc][1] = tf32r(Q[(size_t)(g+8)*H3 + c    ] * 0.125f);
            qf[kc][2] = tf32r(Q[(size_t)g*H3     + c + 4] * 0.125f);
            qf[kc][3] = tf32r(Q[(size_t)(g+8)*H3 + c + 4] * 0.125f);
        }
    }

    float Oc[8][4] = {};
    float m1 = -1e30f, m2 = -1e30f, l1 = 0.f, l2 = 0.f;
    int r1 = q0 + wm + g, r2 = r1 + 8;

    for (int j0 = 0; j0 < q0 + FBM; j0 += 64) {
        __syncthreads();
        // load K (transpose to [d][kv]) and V ([kv][d]) tiles, tf32
        {
            int r = tid & 63;
            int cb = (tid >> 6) * 16;
            const float* K = qkv + (size_t)(j0+r)*H3 + HID   + h*HD;
            const float* V = qkv + (size_t)(j0+r)*H3 + 2*HID + h*HD;
#pragma unroll
            for (int i = 0; i < 4; i++) {
                int c = cb + i*4;
                float4 kv4 = *(const float4*)(K + c);
                Ks[c+0][r] = tf32r(kv4.x); Ks[c+1][r] = tf32r(kv4.y);
                Ks[c+2][r] = tf32r(kv4.z); Ks[c+3][r] = tf32r(kv4.w);
                float4 vv = *(const float4*)(V + c);
                Vs[r][c+0] = tf32r(vv.x); Vs[r][c+1] = tf32r(vv.y);
                Vs[r][c+2] = tf32r(vv.z); Vs[r][c+3] = tf32r(vv.w);
            }
        }
        __syncthreads();

        // S = Q K^T
        float Sc[8][4];
#pragma unroll
        for (int j = 0; j < 8; j++) {
            Sc[j][0] = Sc[j][1] = Sc[j][2] = Sc[j][3] = 0.f;
#pragma unroll
            for (int kc = 0; kc < 8; kc++) {
                float b0 = Ks[kc*8+tg  ][j*8+g];
                float b1 = Ks[kc*8+tg+4][j*8+g];
                mma8(Sc[j], qf[kc][0], qf[kc][1], qf[kc][2], qf[kc][3], b0, b1);
            }
        }
        // causal mask (only tiles near/above diagonal of this warp's rows)
        if (j0 + 63 > q0 + wm) {
#pragma unroll
            for (int j = 0; j < 8; j++) {
                int cb = j0 + j*8 + 2*tg;
                if (cb   > r1) Sc[j][0] = -1e30f;
                if (cb+1 > r1) Sc[j][1] = -1e30f;
                if (cb   > r2) Sc[j][2] = -1e30f;
                if (cb+1 > r2) Sc[j][3] = -1e30f;
            }
        }
        // online softmax
        float mx1 = -1e30f, mx2 = -1e30f;
#pragma unroll
        for (int j = 0; j < 8; j++) {
            mx1 = fmaxf(mx1, fmaxf(Sc[j][0], Sc[j][1]));
            mx2 = fmaxf(mx2, fmaxf(Sc[j][2], Sc[j][3]));
        }
        mx1 = fmaxf(mx1, __shfl_xor_sync(0xffffffffu, mx1, 1));
        mx1 = fmaxf(mx1, __shfl_xor_sync(0xffffffffu, mx1, 2));
        mx2 = fmaxf(mx2, __shfl_xor_sync(0xffffffffu, mx2, 1));
        mx2 = fmaxf(mx2, __shfl_xor_sync(0xffffffffu, mx2, 2));
        float nm1 = fmaxf(m1, mx1), nm2 = fmaxf(m2, mx2);
        float al1 = __expf(m1 - nm1), al2 = __expf(m2 - nm2);
        float s1 = 0.f, s2 = 0.f;
#pragma unroll
        for (int j = 0; j < 8; j++) {
            Sc[j][0] = __expf(Sc[j][0] - nm1);
            Sc[j][1] = __expf(Sc[j][1] - nm1);
            Sc[j][2] = __expf(Sc[j][2] - nm2);
            Sc[j][3] = __expf(Sc[j][3] - nm2);
            s1 += Sc[j][0] + Sc[j][1];
            s2 += Sc[j][2] + Sc[j][3];
        }
        s1 += __shfl_xor_sync(0xffffffffu, s1, 1);
        s1 += __shfl_xor_sync(0xffffffffu, s1, 2);
        s2 += __shfl_xor_sync(0xffffffffu, s2, 1);
        s2 += __shfl_xor_sync(0xffffffffu, s2, 2);
        l1 = l1*al1 + s1; l2 = l2*al2 + s2;
        m1 = nm1; m2 = nm2;
#pragma unroll
        for (int jd = 0; jd < 8; jd++) {
            Oc[jd][0] *= al1; Oc[jd][1] *= al1;
            Oc[jd][2] *= al2; Oc[jd][3] *= al2;
        }
        // P to tf32
#pragma unroll
        for (int j = 0; j < 8; j++) {
            Sc[j][0] = tf32r(Sc[j][0]); Sc[j][1] = tf32r(Sc[j][1]);
            Sc[j][2] = tf32r(Sc[j][2]); Sc[j][3] = tf32r(Sc[j][3]);
        }
        // O += P V  (C-frag -> A-frag via shfl)
        int lane0 = (g<<2) + (tg>>1);
        int sel = tg & 1;
#pragma unroll
        for (int kc = 0; kc < 8; kc++) {
            float u0 = __shfl_sync(0xffffffffu, Sc[kc][0], lane0);
            float u1 = __shfl_sync(0xffffffffu, Sc[kc][1], lane0);
            float a0 = sel ? u1 : u0;
            float u2 = __shfl_sync(0xffffffffu, Sc[kc][2], lane0);
            float u3 = __shfl_sync(0xffffffffu, Sc[kc][3], lane0);
            float a1 = sel ? u3 : u2;
            float u4 = __shfl_sync(0xffffffffu, Sc[kc][0], lane0+2);
            float u5 = __shfl_sync(0xffffffffu, Sc[kc][1], lane0+2);
            float a2 = sel ? u5 : u4;
            float u6 = __shfl_sync(0xffffffffu, Sc[kc][2], lane0+2);
            float u7 = __shfl_sync(0xffffffffu, Sc[kc][3], lane0+2);
            float a3 = sel ? u7 : u6;
#pragma unroll
            for (int jd = 0; jd < 8; jd++) {
                float b0 = Vs[kc*8+tg  ][jd*8+g];
                float b1 = Vs[kc*8+tg+4][jd*8+g];
                mma8(Oc[jd], a0, a1, a2, a3, b0, b1);
            }
        }
    }

    float inv1 = 1.f / l1, inv2 = 1.f / l2;
#pragma unroll
    for (int jd = 0; jd < 8; jd++) {
        int c = h*HD + jd*8 + 2*tg;
        *(float2*)(attn + (size_t)r1*HID + c) = make_float2(Oc[jd][0]*inv1, Oc[jd][1]*inv1);
        *(float2*)(attn + (size_t)r2*HID + c) = make_float2(Oc[jd][2]*inv2, Oc[jd][3]*inv2);
    }
}

// ---------------- router ----------------
__global__ void router_kernel(const float* __restrict__ hn2, const float* __restrict__ rw) {
    int t = blockIdx.x, tid = threadIdx.x;
    __shared__ float part[NE][256];
    float loc[NE] = {};
    for (int hh = tid; hh < HID; hh += 256) {
        float xv = hn2[(size_t)t*HID + hh];
#pragma unroll
        for (int e = 0; e < NE; e++) loc[e] += xv * rw[e*HID + hh];
    }
#pragma unroll
    for (int e = 0; e < NE; e++) part[e][tid] = loc[e];
    __syncthreads();
    for (int o = 128; o > 0; o >>= 1) {
        if (tid < o)
#pragma unroll
            for (int e = 0; e < NE; e++) part[e][tid] += part[e][tid+o];
        __syncthreads();
    }
    if (tid == 0) {
        float lg[NE], mx = -1e30f;
#pragma unroll
        for (int e = 0; e < NE; e++) { lg[e] = part[e][0]; mx = fmaxf(mx, lg[e]); }
        float s = 0.f;
#pragma unroll
        for (int e = 0; e < NE; e++) { lg[e] = expf(lg[e]-mx); s += lg[e]; }
        float inv = 1.0f/s;
#pragma unroll
        for (int e = 0; e < NE; e++) lg[e] *= inv;
        int i0 = 0; float v0 = lg[0];
#pragma unroll
        for (int e = 1; e < NE; e++) if (lg[e] > v0) { v0 = lg[e]; i0 = e; }
        int i1 = -1; float v1 = -1e30f;
#pragma unroll
        for (int e = 0; e < NE; e++) if (e != i0 && lg[e] > v1) { v1 = lg[e]; i1 = e; }
        g_topi[t*TK+0] = i0; g_topw[t*TK+0] = v0;
        g_topi[t*TK+1] = i1; g_topw[t*TK+1] = v1;
    }
}

// ---------------- deterministic expert lists ----------------
__global__ void build_lists_kernel() {
    int e = blockIdx.x, tid = threadIdx.x;
    const int CH = SQ / 256;
    int ids[CH], slots[CH]; float gs[CH];
    int loc = 0;
    for (int c = 0; c < CH; c++) {
        int t = tid*CH + c;
        if (g_topi[t*TK+0] == e)      { ids[loc]=t; slots[loc]=0; gs[loc]=g_topw[t*TK+0]; loc++; }
        else if (g_topi[t*TK+1] == e) { ids[loc]=t; slots[loc]=1; gs[loc]=g_topw[t*TK+1]; loc++; }
    }
    __shared__ int sc[256];
    sc[tid] = loc; __syncthreads();
    for (int o = 1; o < 256; o <<= 1) {
        int v = (tid >= o) ? sc[tid-o] : 0;
        __syncthreads();
        sc[tid] += v;
        __syncthreads();
    }
    int off = sc[tid] - loc;
    for (int c = 0; c < loc; c++) {
        g_tok [e*SQ + off + c] = ids[c];
        g_slot[e*SQ + off + c] = slots[c];
        g_gate[e*SQ + off + c] = gs[c];
    }
    if (tid == 255) g_cnt[e] = sc[255];
}

// ---------------- out = x1 + y2[:,0] + y2[:,1] ----------------
__global__ void final_kernel(float* __restrict__ out) {
    int idx = blockIdx.x * 256 + threadIdx.x;
    int t = idx / HID, hh = idx % HID;
    out[idx] = g_x1[idx] + g_y2[((size_t)t*TK)*HID + hh] + g_y2[((size_t)t*TK + 1)*HID + hh];
}

// ---------------- launch ----------------
extern "C" void kernel_launch(void* const* d_in, const int* in_sizes, int n_in,
                              void* d_out, int out_size) {
    (void)in_sizes; (void)n_in; (void)out_size;
    const float* x          = (const float*)d_in[0];
    const float* ln1_w      = (const float*)d_in[1];
    const float* ln1_b      = (const float*)d_in[2];
    const float* in_proj_w  = (const float*)d_in[3];
    const float* in_proj_b  = (const float*)d_in[4];
    const float* out_proj_w = (const float*)d_in[5];
    const float* out_proj_b = (const float*)d_in[6];
    const float* ln2_w      = (const float*)d_in[7];
    const float* ln2_b      = (const float*)d_in[8];
    const float* router_w   = (const float*)d_in[9];
    const float* w1         = (const float*)d_in[10];
    const float* w2         = (const float*)d_in[11];
    float* out = (float*)d_out;

    float *hn, *qkv, *attn, *x1, *hn2;
    cudaGetSymbolAddress((void**)&hn,   g_hn);
    cudaGetSymbolAddress((void**)&qkv,  g_qkv);
    cudaGetSymbolAddress((void**)&attn, g_attn);
    cudaGetSymbolAddress((void**)&x1,   g_x1);
    cudaGetSymbolAddress((void**)&hn2,  g_hn2);

    ln_kernel<<<SQ, 256>>>(x, ln1_w, ln1_b, hn);
    mma_gemm<0><<<dim3(H3/BN, SQ/BM), 256>>>(hn, in_proj_w, in_proj_b, nullptr, qkv, SQ, H3, HID);
    flash_kernel<<<dim3(SQ/FBM, NH), 256>>>(qkv, attn);
    mma_gemm<1><<<dim3(HID/BN, SQ/BM), 256>>>(attn, out_proj_w, out_proj_b, x, x1, SQ, HID, HID);
    ln_kernel<<<SQ, 256>>>(x1, ln2_w, ln2_b, hn2);
    router_kernel<<<SQ, 256>>>(hn2, router_w);
    build_lists_kernel<<<NE, 256>>>();
    mma_gemm<2><<<dim3(FF/BN, SQ/BM, NE), 256>>>(hn2, w1, nullptr, nullptr, nullptr, SQ, FF, HID);
    mma_gemm<3><<<dim3(HID/BN, SQ/BM, NE), 256>>>(nullptr, w2, nullptr, nullptr, nullptr, SQ, HID, FF);
    final_kernel<<<(SQ*HID)/256, 256>>>(out);
}

// round 6
// speedup vs baseline: 2.8094x; 1.0508x over previous
#include <cuda_runtime.h>
#include <math.h>
#include <stdint.h>

#define SQ   2048
#define HID  1024
#define NH   16
#define HD   64
#define H3   3072
#define NE   8
#define TK   2
#define FF   2048

// ---------------- scratch ----------------
__device__ float g_hn   [SQ*HID];
__device__ float g_qkv  [SQ*H3];
__device__ float g_attn [SQ*HID];
__device__ float g_x1   [SQ*HID];
__device__ float g_hn2  [SQ*HID];
__device__ int   g_topi [SQ*TK];
__device__ float g_topw [SQ*TK];
__device__ int   g_tok  [NE*SQ];
__device__ float g_gate [NE*SQ];
__device__ int   g_slot [NE*SQ];
__device__ int   g_cnt  [NE];
__device__ float g_h1   [(size_t)NE*SQ*FF];
__device__ float g_y2   [SQ*TK*HID];

// ---------------- helpers ----------------
__device__ __forceinline__ float tf32r(float x) {
    uint32_t u; asm("cvt.rna.tf32.f32 %0, %1;" : "=r"(u) : "f"(x));
    return __uint_as_float(u);
}
__device__ __forceinline__ void mma8(float* c, float a0, float a1, float a2, float a3,
                                     float b0, float b1) {
    uint32_t A0=__float_as_uint(a0), A1=__float_as_uint(a1),
             A2=__float_as_uint(a2), A3=__float_as_uint(a3),
             B0=__float_as_uint(b0), B1=__float_as_uint(b1);
    asm volatile("mma.sync.aligned.m16n8k8.row.col.f32.tf32.tf32.f32 "
        "{%0,%1,%2,%3},{%4,%5,%6,%7},{%8,%9},{%0,%1,%2,%3};\n"
        : "+f"(c[0]), "+f"(c[1]), "+f"(c[2]), "+f"(c[3])
        : "r"(A0), "r"(A1), "r"(A2), "r"(A3), "r"(B0), "r"(B1));
}
__device__ __forceinline__ uint32_t sptr(const void* p) {
    return (uint32_t)__cvta_generic_to_shared(p);
}
__device__ __forceinline__ void cp16(uint32_t s, const void* g, bool v) {
    int sz = v ? 16 : 0;
    asm volatile("cp.async.cg.shared.global [%0], [%1], 16, %2;\n"
                 :: "r"(s), "l"(g), "r"(sz));
}
#define CP_COMMIT() asm volatile("cp.async.commit_group;\n")
#define CP_WAIT0()  asm volatile("cp.async.wait_group 0;\n")

__device__ __forceinline__ float gelu_exact(float x) {
    return 0.5f * x * (1.0f + erff(x * 0.70710678118654752f));
}

// ---------------- layernorm ----------------
__global__ void ln_kernel(const float* __restrict__ x, const float* __restrict__ w,
                          const float* __restrict__ b, float* __restrict__ out) {
    int t = blockIdx.x, tid = threadIdx.x;
    float4 v = ((const float4*)(x + (size_t)t*HID))[tid];
    __shared__ float red[256];
    red[tid] = v.x+v.y+v.z+v.w; __syncthreads();
    for (int o = 128; o > 0; o >>= 1) { if (tid < o) red[tid] += red[tid+o]; __syncthreads(); }
    float mu = red[0] * (1.0f/HID); __syncthreads();
    float dx=v.x-mu, dy=v.y-mu, dz=v.z-mu, dw=v.w-mu;
    red[tid] = dx*dx+dy*dy+dz*dz+dw*dw; __syncthreads();
    for (int o = 128; o > 0; o >>= 1) { if (tid < o) red[tid] += red[tid+o]; __syncthreads(); }
    float rstd = rsqrtf(red[0] * (1.0f/HID) + 1e-5f);
    float4 wv = ((const float4*)w)[tid];
    float4 bv = ((const float4*)b)[tid];
    float4 o4;
    o4.x = dx*rstd*wv.x + bv.x; o4.y = dy*rstd*wv.y + bv.y;
    o4.z = dz*rstd*wv.z + bv.z; o4.w = dw*rstd*wv.w + bv.w;
    ((float4*)(out + (size_t)t*HID))[tid] = o4;
}

// ================= tf32 mma GEMM, cp.async double-buffered =================
// MODE 0: QKV  (NT, +bias)     MODE 1: OUT (NT, +bias +res)
// MODE 2: MOE1 (NN, gather A, gelu -> g_h1)
// MODE 3: MOE2 (NN, A=g_h1, gate*scatter -> g_y2)
#define BM 128
#define BN 128
#define BKg 16
#define ASTR (BKg+4)   // 20
#define BSTR_NN (BN+8) // 136

template<int MODE>
__global__ void __launch_bounds__(256,2) mma_gemm(
        const float* __restrict__ A, const float* __restrict__ Bm,
        const float* __restrict__ bias, const float* __restrict__ res,
        float* __restrict__ C, int M, int N, int Kd) {
    __shared__ float As[2][BM*ASTR];
    __shared__ float Bs[2][BM*ASTR];
    int tid = threadIdx.x, wid = tid>>5, lid = tid&31;
    int g = lid>>2, tg = lid&3;
    int wm = (wid>>2)*64, wn = (wid&3)*32;
    int n0 = blockIdx.x*BN, m0 = blockIdx.y*BM;

    int e = 0, cnt = M;
    if (MODE >= 2) { e = blockIdx.z; cnt = g_cnt[e]; if (m0 >= cnt) return; }

    int arow = tid>>1;
    int ka   = (tid&1)*8;
    const float* Aptr = A;
    bool av = true;
    if (MODE <= 1) {
        Aptr = A + (size_t)(m0+arow)*Kd;
    } else if (MODE == 2) {
        int t = (m0+arow < cnt) ? g_tok[e*SQ + m0 + arow] : -1;
        av = (t >= 0);
        Aptr = A + (size_t)(av ? t : 0)*Kd;
    } else {
        int rr = m0 + arow; if (rr > SQ-1) rr = SQ-1;
        Aptr = g_h1 + (size_t)(e*SQ + rr)*Kd;
    }
    const float* Bbase = Bm;
    if (MODE >= 2) Bbase += (size_t)e * Kd * N;

    int bkr = tid>>4, bnc = (tid&15)*4;

    auto issue = [&](int kt, int s) {
        uint32_t da = sptr(&As[s][arow*ASTR + ka]);
        const float* ga = Aptr + kt*BKg + ka;
        cp16(da,      ga,     av);
        cp16(da + 16, ga + 4, av);
        if (MODE <= 1) {
            uint32_t db = sptr(&Bs[s][arow*ASTR + ka]);
            const float* gb = Bbase + (size_t)(n0+arow)*Kd + kt*BKg + ka;
            cp16(db,      gb,     true);
            cp16(db + 16, gb + 4, true);
        } else {
            uint32_t db = sptr(&Bs[s][bkr*BSTR_NN + bnc]);
            const float* gb = Bbase + (size_t)(kt*BKg+bkr)*N + n0 + bnc;
            cp16(db,       gb,      true);
            cp16(db + 256, gb + 64, true);
        }
        CP_COMMIT();
    };

    float acc[4][4][4] = {};
    int KT = Kd / BKg;
    issue(0, 0);
    for (int kt = 0; kt < KT; kt++) {
        CP_WAIT0();
        __syncthreads();
        if (kt+1 < KT) issue(kt+1, (kt+1)&1);
        const float* as = As[kt&1];
        const float* bs = Bs[kt&1];
#pragma unroll
        for (int ks = 0; ks < 2; ks++) {
            float af[4][4], bf[4][2];
            int k0 = ks*8 + tg;
#pragma unroll
            for (int mi = 0; mi < 4; mi++) {
                int rb = wm + mi*16;
                af[mi][0] = tf32r(as[(rb+g  )*ASTR + k0]);
                af[mi][1] = tf32r(as[(rb+g+8)*ASTR + k0]);
                af[mi][2] = tf32r(as[(rb+g  )*ASTR + k0+4]);
                af[mi][3] = tf32r(as[(rb+g+8)*ASTR + k0+4]);
            }
#pragma unroll
            for (int ni = 0; ni < 4; ni++) {
                int nc = wn + ni*8 + g;
                if (MODE <= 1) {
                    bf[ni][0] = tf32r(bs[nc*ASTR + k0]);
                    bf[ni][1] = tf32r(bs[nc*ASTR + k0+4]);
                } else {
                    bf[ni][0] = tf32r(bs[(k0  )*BSTR_NN + nc]);
                    bf[ni][1] = tf32r(bs[(k0+4)*BSTR_NN + nc]);
                }
            }
#pragma unroll
            for (int mi = 0; mi < 4; mi++)
#pragma unroll
                for (int ni = 0; ni < 4; ni++)
                    mma8(acc[mi][ni], af[mi][0], af[mi][1], af[mi][2], af[mi][3],
                         bf[ni][0], bf[ni][1]);
        }
        __syncthreads();
    }

    // ---- epilogue ----
#pragma unroll
    for (int mi = 0; mi < 4; mi++) {
        int r1 = m0 + wm + mi*16 + g;
        int r2 = r1 + 8;
#pragma unroll
        for (int ni = 0; ni < 4; ni++) {
            int cc = n0 + wn + ni*8 + 2*tg;
            float* a = acc[mi][ni];
            if (MODE == 0 || MODE == 1) {
                float b0 = bias[cc], b1 = bias[cc+1];
                float v00 = a[0]+b0, v01 = a[1]+b1, v10 = a[2]+b0, v11 = a[3]+b1;
                if (MODE == 1) {
                    v00 += res[(size_t)r1*N + cc];   v01 += res[(size_t)r1*N + cc+1];
                    v10 += res[(size_t)r2*N + cc];   v11 += res[(size_t)r2*N + cc+1];
                }
                *(float2*)(C + (size_t)r1*N + cc) = make_float2(v00, v01);
                *(float2*)(C + (size_t)r2*N + cc) = make_float2(v10, v11);
            } else if (MODE == 2) {
                if (r1 < cnt)
                    *(float2*)(&g_h1[(size_t)(e*SQ + r1)*FF + cc]) =
                        make_float2(gelu_exact(a[0]), gelu_exact(a[1]));
                if (r2 < cnt)
                    *(float2*)(&g_h1[(size_t)(e*SQ + r2)*FF + cc]) =
                        make_float2(gelu_exact(a[2]), gelu_exact(a[3]));
            } else {
                if (r1 < cnt) {
                    int t = g_tok[e*SQ+r1], sl = g_slot[e*SQ+r1];
                    float gt = g_gate[e*SQ+r1];
                    *(float2*)(&g_y2[((size_t)t*TK+sl)*HID + cc]) =
                        make_float2(gt*a[0], gt*a[1]);
                }
                if (r2 < cnt) {
                    int t = g_tok[e*SQ+r2], sl = g_slot[e*SQ+r2];
                    float gt = g_gate[e*SQ+r2];
                    *(float2*)(&g_y2[((size_t)t*TK+sl)*HID + cc]) =
                        make_float2(gt*a[2], gt*a[3]);
                }
            }
        }
    }
}

// ================= flash attention (tf32 mma, online softmax) =================
#define FBM 128
__global__ void __launch_bounds__(256) flash_kernel(const float* __restrict__ qkv,
                                                    float* __restrict__ attn) {
    int h = blockIdx.y;
    int q0 = blockIdx.x * FBM;
    int tid = threadIdx.x, wid = tid>>5, lid = tid&31;
    int wm = wid*16;
    int g = lid>>2, tg = lid&3;
    __shared__ float Kv[64*68];   // [kv][d], stride 68
    __shared__ float Vs[64*72];   // [kv][d], stride 72

    float qf[8][4];
    {
        const float* Q = qkv + (size_t)(q0+wm)*H3 + h*HD;
#pragma unroll
        for (int kc = 0; kc < 8; kc++) {
            int c = kc*8 + tg;
            qf[kc][0] = tf32r(Q[(size_t)g*H3     + c    ] * 0.125f);
            qf[kc][1] = tf32r(Q[(size_t)(g+8)*H3 + c    ] * 0.125f);
            qf[kc][2] = tf32r(Q[(size_t)g*H3     + c + 4] * 0.125f);
            qf[kc][3] = tf32r(Q[(size_t)(g+8)*H3 + c + 4] * 0.125f);
        }
    }

    float Oc[8][4] = {};
    float m1 = -1e30f, m2 = -1e30f, l1 = 0.f, l2 = 0.f;
    int r1 = q0 + wm + g, r2 = r1 + 8;

    for (int j0 = 0; j0 < q0 + FBM; j0 += 64) {
        __syncthreads();
        {
            int r = tid & 63;
            int cb = (tid >> 6) * 16;
            const float* K = qkv + (size_t)(j0+r)*H3 + HID   + h*HD;
            const float* V = qkv + (size_t)(j0+r)*H3 + 2*HID + h*HD;
#pragma unroll
            for (int i = 0; i < 4; i++) {
                int c = cb + i*4;
                *(float4*)(&Kv[r*68 + c]) = *(const float4*)(K + c);
                *(float4*)(&Vs[r*72 + c]) = *(const float4*)(V + c);
            }
        }
        __syncthreads();

        // S = Q K^T
        float Sc[8][4];
#pragma unroll
        for (int j = 0; j < 8; j++) {
            Sc[j][0] = Sc[j][1] = Sc[j][2] = Sc[j][3] = 0.f;
#pragma unroll
            for (int kc = 0; kc < 8; kc++) {
                float b0 = tf32r(Kv[(j*8+g)*68 + kc*8+tg]);
                float b1 = tf32r(Kv[(j*8+g)*68 + kc*8+tg+4]);
                mma8(Sc[j], qf[kc][0], qf[kc][1], qf[kc][2], qf[kc][3], b0, b1);
            }
        }
        if (j0 + 63 > q0 + wm) {
#pragma unroll
            for (int j = 0; j < 8; j++) {
                int cb = j0 + j*8 + 2*tg;
                if (cb   > r1) Sc[j][0] = -1e30f;
                if (cb+1 > r1) Sc[j][1] = -1e30f;
                if (cb   > r2) Sc[j][2] = -1e30f;
                if (cb+1 > r2) Sc[j][3] = -1e30f;
            }
        }
        float mx1 = -1e30f, mx2 = -1e30f;
#pragma unroll
        for (int j = 0; j < 8; j++) {
            mx1 = fmaxf(mx1, fmaxf(Sc[j][0], Sc[j][1]));
            mx2 = fmaxf(mx2, fmaxf(Sc[j][2], Sc[j][3]));
        }
        mx1 = fmaxf(mx1, __shfl_xor_sync(0xffffffffu, mx1, 1));
        mx1 = fmaxf(mx1, __shfl_xor_sync(0xffffffffu, mx1, 2));
        mx2 = fmaxf(mx2, __shfl_xor_sync(0xffffffffu, mx2, 1));
        mx2 = fmaxf(mx2, __shfl_xor_sync(0xffffffffu, mx2, 2));
        float nm1 = fmaxf(m1, mx1), nm2 = fmaxf(m2, mx2);
        float al1 = __expf(m1 - nm1), al2 = __expf(m2 - nm2);
        float s1 = 0.f, s2 = 0.f;
#pragma unroll
        for (int j = 0; j < 8; j++) {
            Sc[j][0] = __expf(Sc[j][0] - nm1);
            Sc[j][1] = __expf(Sc[j][1] - nm1);
            Sc[j][2] = __expf(Sc[j][2] - nm2);
            Sc[j][3] = __expf(Sc[j][3] - nm2);
            s1 += Sc[j][0] + Sc[j][1];
            s2 += Sc[j][2] + Sc[j][3];
        }
        s1 += __shfl_xor_sync(0xffffffffu, s1, 1);
        s1 += __shfl_xor_sync(0xffffffffu, s1, 2);
        s2 += __shfl_xor_sync(0xffffffffu, s2, 1);
        s2 += __shfl_xor_sync(0xffffffffu, s2, 2);
        l1 = l1*al1 + s1; l2 = l2*al2 + s2;
        m1 = nm1; m2 = nm2;
#pragma unroll
        for (int jd = 0; jd < 8; jd++) {
            Oc[jd][0] *= al1; Oc[jd][1] *= al1;
            Oc[jd][2] *= al2; Oc[jd][3] *= al2;
        }
#pragma unroll
        for (int j = 0; j < 8; j++) {
            Sc[j][0] = tf32r(Sc[j][0]); Sc[j][1] = tf32r(Sc[j][1]);
            Sc[j][2] = tf32r(Sc[j][2]); Sc[j][3] = tf32r(Sc[j][3]);
        }
        int lane0 = (g<<2) + (tg>>1);
        int sel = tg & 1;
#pragma unroll
        for (int kc = 0; kc < 8; kc++) {
            float u0 = __shfl_sync(0xffffffffu, Sc[kc][0], lane0);
            float u1 = __shfl_sync(0xffffffffu, Sc[kc][1], lane0);
            float a0 = sel ? u1 : u0;
            float u2 = __shfl_sync(0xffffffffu, Sc[kc][2], lane0);
            float u3 = __shfl_sync(0xffffffffu, Sc[kc][3], lane0);
            float a1 = sel ? u3 : u2;
            float u4 = __shfl_sync(0xffffffffu, Sc[kc][0], lane0+2);
            float u5 = __shfl_sync(0xffffffffu, Sc[kc][1], lane0+2);
            float a2 = sel ? u5 : u4;
            float u6 = __shfl_sync(0xffffffffu, Sc[kc][2], lane0+2);
            float u7 = __shfl_sync(0xffffffffu, Sc[kc][3], lane0+2);
            float a3 = sel ? u7 : u6;
#pragma unroll
            for (int jd = 0; jd < 8; jd++) {
                float b0 = tf32r(Vs[(kc*8+tg  )*72 + jd*8+g]);
                float b1 = tf32r(Vs[(kc*8+tg+4)*72 + jd*8+g]);
                mma8(Oc[jd], a0, a1, a2, a3, b0, b1);
            }
        }
    }

    float inv1 = 1.f / l1, inv2 = 1.f / l2;
#pragma unroll
    for (int jd = 0; jd < 8; jd++) {
        int c = h*HD + jd*8 + 2*tg;
        *(float2*)(attn + (size_t)r1*HID + c) = make_float2(Oc[jd][0]*inv1, Oc[jd][1]*inv1);
        *(float2*)(attn + (size_t)r2*HID + c) = make_float2(Oc[jd][2]*inv2, Oc[jd][3]*inv2);
    }
}

// ---------------- router ----------------
__global__ void router_kernel(const float* __restrict__ hn2, const float* __restrict__ rw) {
    int t = blockIdx.x, tid = threadIdx.x;
    __shared__ float part[NE][256];
    float loc[NE] = {};
    for (int hh = tid; hh < HID; hh += 256) {
        float xv = hn2[(size_t)t*HID + hh];
#pragma unroll
        for (int e = 0; e < NE; e++) loc[e] += xv * rw[e*HID + hh];
    }
#pragma unroll
    for (int e = 0; e < NE; e++) part[e][tid] = loc[e];
    __syncthreads();
    for (int o = 128; o > 0; o >>= 1) {
        if (tid < o)
#pragma unroll
            for (int e = 0; e < NE; e++) part[e][tid] += part[e][tid+o];
        __syncthreads();
    }
    if (tid == 0) {
        float lg[NE], mx = -1e30f;
#pragma unroll
        for (int e = 0; e < NE; e++) { lg[e] = part[e][0]; mx = fmaxf(mx, lg[e]); }
        float s = 0.f;
#pragma unroll
        for (int e = 0; e < NE; e++) { lg[e] = expf(lg[e]-mx); s += lg[e]; }
        float inv = 1.0f/s;
#pragma unroll
        for (int e = 0; e < NE; e++) lg[e] *= inv;
        int i0 = 0; float v0 = lg[0];
#pragma unroll
        for (int e = 1; e < NE; e++) if (lg[e] > v0) { v0 = lg[e]; i0 = e; }
        int i1 = -1; float v1 = -1e30f;
#pragma unroll
        for (int e = 0; e < NE; e++) if (e != i0 && lg[e] > v1) { v1 = lg[e]; i1 = e; }
        g_topi[t*TK+0] = i0; g_topw[t*TK+0] = v0;
        g_topi[t*TK+1] = i1; g_topw[t*TK+1] = v1;
    }
}

// ---------------- deterministic expert lists ----------------
__global__ void build_lists_kernel() {
    int e = blockIdx.x, tid = threadIdx.x;
    const int CH = SQ / 256;
    int ids[CH], slots[CH]; float gs[CH];
    int loc = 0;
    for (int c = 0; c < CH; c++) {
        int t = tid*CH + c;
        if (g_topi[t*TK+0] == e)      { ids[loc]=t; slots[loc]=0; gs[loc]=g_topw[t*TK+0]; loc++; }
        else if (g_topi[t*TK+1] == e) { ids[loc]=t; slots[loc]=1; gs[loc]=g_topw[t*TK+1]; loc++; }
    }
    __shared__ int sc[256];
    sc[tid] = loc; __syncthreads();
    for (int o = 1; o < 256; o <<= 1) {
        int v = (tid >= o) ? sc[tid-o] : 0;
        __syncthreads();
        sc[tid] += v;
        __syncthreads();
    }
    int off = sc[tid] - loc;
    for (int c = 0; c < loc; c++) {
        g_tok [e*SQ + off + c] = ids[c];
        g_slot[e*SQ + off + c] = slots[c];
        g_gate[e*SQ + off + c] = gs[c];
    }
    if (tid == 255) g_cnt[e] = sc[255];
}

// ---------------- out = x1 + y2[:,0] + y2[:,1] ----------------
__global__ void final_kernel(float* __restrict__ out) {
    int idx = blockIdx.x * 256 + threadIdx.x;
    int t = idx / HID, hh = idx % HID;
    out[idx] = g_x1[idx] + g_y2[((size_t)t*TK)*HID + hh] + g_y2[((size_t)t*TK + 1)*HID + hh];
}

// ---------------- launch ----------------
extern "C" void kernel_launch(void* const* d_in, const int* in_sizes, int n_in,
                              void* d_out, int out_size) {
    (void)in_sizes; (void)n_in; (void)out_size;
    const float* x          = (const float*)d_in[0];
    const float* ln1_w      = (const float*)d_in[1];
    const float* ln1_b      = (const float*)d_in[2];
    const float* in_proj_w  = (const float*)d_in[3];
    const float* in_proj_b  = (const float*)d_in[4];
    const float* out_proj_w = (const float*)d_in[5];
    const float* out_proj_b = (const float*)d_in[6];
    const float* ln2_w      = (const float*)d_in[7];
    const float* ln2_b      = (const float*)d_in[8];
    const float* router_w   = (const float*)d_in[9];
    const float* w1         = (const float*)d_in[10];
    const float* w2         = (const float*)d_in[11];
    float* out = (float*)d_out;

    float *hn, *qkv, *attn, *x1, *hn2;
    cudaGetSymbolAddress((void**)&hn,   g_hn);
    cudaGetSymbolAddress((void**)&qkv,  g_qkv);
    cudaGetSymbolAddress((void**)&attn, g_attn);
    cudaGetSymbolAddress((void**)&x1,   g_x1);
    cudaGetSymbolAddress((void**)&hn2,  g_hn2);

    ln_kernel<<<SQ, 256>>>(x, ln1_w, ln1_b, hn);
    mma_gemm<0><<<dim3(H3/BN, SQ/BM), 256>>>(hn, in_proj_w, in_proj_b, nullptr, qkv, SQ, H3, HID);
    flash_kernel<<<dim3(SQ/FBM, NH), 256>>>(qkv, attn);
    mma_gemm<1><<<dim3(HID/BN, SQ/BM), 256>>>(attn, out_proj_w, out_proj_b, x, x1, SQ, HID, HID);
    ln_kernel<<<SQ, 256>>>(x1, ln2_w, ln2_b, hn2);
    router_kernel<<<SQ, 256>>>(hn2, router_w);
    build_lists_kernel<<<NE, 256>>>();
    mma_gemm<2><<<dim3(FF/BN, SQ/BM, NE), 256>>>(hn2, w1, nullptr, nullptr, nullptr, SQ, FF, HID);
    mma_gemm<3><<<dim3(HID/BN, SQ/BM, NE), 256>>>(nullptr, w2, nullptr, nullptr, nullptr, SQ, HID, FF);
    final_kernel<<<(SQ*HID)/256, 256>>>(out);
}